// round 5
// baseline (speedup 1.0000x reference)
#include <cuda_runtime.h>

#define BB 4
#define LQ 256
#define LK 256
#define DD 768

// Scratch (no cudaMalloc allowed)
__device__ float g_q[BB*LQ*DD];
__device__ float g_k[BB*LK*DD];
__device__ float g_v[BB*LK*DD];
__device__ float g_scores[BB*LQ*LK];

__device__ __forceinline__ float tanh_fast(float x) {
    float y;
    asm("tanh.approx.f32 %0, %1;" : "=f"(y) : "f"(x));
    return y;
}

// ---- packed fp32x2 helpers (Blackwell FFMA2 path) ----
__device__ __forceinline__ void ffma2(unsigned long long& acc,
                                      unsigned long long a,
                                      unsigned long long b) {
    asm("fma.rn.f32x2 %0, %1, %2, %0;" : "+l"(acc) : "l"(a), "l"(b));
}
__device__ __forceinline__ float2 unpack2(unsigned long long v) {
    float lo, hi;
    asm("mov.b64 {%0, %1}, %2;" : "=f"(lo), "=f"(hi) : "l"(v));
    return make_float2(lo, hi);
}
__device__ __forceinline__ float2 dup2(float x) { return make_float2(x, x); }

// ---------------------------------------------------------------------------
// Projection GEMM: Out[M,N] = X[M,K] @ W[K,N] + b[N].  M=1024, N=K=768.
// 64x128 tile, 256 threads, grid 288 (~2 blocks/SM). BK=16 double-buffered.
// A stored DUPLICATED in smem ({a,a} pairs) -> FFMA2 a-operands direct from
// LDS.128, no dup-MOVs. Micro 4m x 8n (16 FFMA2/kk).
// ---------------------------------------------------------------------------
__global__ __launch_bounds__(256) void proj_kernel(
    const float* __restrict__ xq, const float* __restrict__ xk, const float* __restrict__ xv,
    const float* __restrict__ Wq, const float* __restrict__ bq,
    const float* __restrict__ Wk, const float* __restrict__ bk,
    const float* __restrict__ Wv, const float* __restrict__ bv)
{
    const int N = DD, K = DD;
    const float *X, *W, *bias;
    float* Out;
    if (blockIdx.z == 0)      { X = xq; W = Wq; bias = bq; Out = g_q; }
    else if (blockIdx.z == 1) { X = xk; W = Wk; bias = bk; Out = g_k; }
    else                      { X = xv; W = Wv; bias = bv; Out = g_v; }

    __shared__ float As2[2][16][132];   // As2[k][2m]={a,a}, 64 m duplicated; padded row
    __shared__ float Bs [2][16][128];   // Bs[k][n]

    const int t  = threadIdx.x;         // 0..255
    const int tx = t & 15;              // n = tx*8 (4 pairs)
    const int ty = t >> 4;              // 0..15, m = ty*4
    const int m0 = blockIdx.y * 64;
    const int n0 = blockIdx.x * 128;

    unsigned long long acc[4][4];
    #pragma unroll
    for (int i = 0; i < 4; i++)
        #pragma unroll
        for (int p = 0; p < 4; p++) acc[i][p] = 0ull;

    // A load: 64 rows x 16 cols = 1024 floats, 1 float4/thread
    const int lr = t >> 2, lc = (t & 3) * 4;
    // B load: 16 rows x 128 cols = 2048 floats, 2 float4/thread
    const int wr = t >> 4, wc = (t & 15) * 8;

    const float* Xp = X + (size_t)(m0 + lr) * K + lc;
    const float* Wp = W + (size_t)wr * N + n0 + wc;

    float4 pa  = *(const float4*)(Xp);
    float4 pb0 = *(const float4*)(Wp);
    float4 pb1 = *(const float4*)(Wp + 4);

    int buf = 0;
    for (int k0 = 0; k0 < K; k0 += 16) {
        *(float2*)&As2[buf][lc+0][2*lr] = dup2(pa.x);
        *(float2*)&As2[buf][lc+1][2*lr] = dup2(pa.y);
        *(float2*)&As2[buf][lc+2][2*lr] = dup2(pa.z);
        *(float2*)&As2[buf][lc+3][2*lr] = dup2(pa.w);
        *(float4*)&Bs[buf][wr][wc]     = pb0;
        *(float4*)&Bs[buf][wr][wc + 4] = pb1;
        __syncthreads();

        if (k0 + 16 < K) {
            pa  = *(const float4*)(Xp + k0 + 16);
            pb0 = *(const float4*)(Wp + (size_t)(k0 + 16) * N);
            pb1 = *(const float4*)(Wp + (size_t)(k0 + 16) * N + 4);
        }

        #pragma unroll
        for (int kk = 0; kk < 16; kk++) {
            ulonglong2 a01 = *(const ulonglong2*)&As2[buf][kk][ty*8];      // {a0,a0},{a1,a1}
            ulonglong2 a23 = *(const ulonglong2*)&As2[buf][kk][ty*8 + 4];  // {a2,a2},{a3,a3}
            ulonglong2 b01 = *(const ulonglong2*)&Bs[buf][kk][tx*8];
            ulonglong2 b23 = *(const ulonglong2*)&Bs[buf][kk][tx*8 + 4];
            unsigned long long aa[4] = { a01.x, a01.y, a23.x, a23.y };
            unsigned long long bb[4] = { b01.x, b01.y, b23.x, b23.y };
            #pragma unroll
            for (int i = 0; i < 4; i++)
                #pragma unroll
                for (int p = 0; p < 4; p++) ffma2(acc[i][p], aa[i], bb[p]);
        }
        buf ^= 1;
    }

    #pragma unroll
    for (int i = 0; i < 4; i++) {
        const int m = m0 + ty*4 + i;
        const int n = n0 + tx*8;
        float2 p0 = unpack2(acc[i][0]);
        float2 p1 = unpack2(acc[i][1]);
        float2 p2 = unpack2(acc[i][2]);
        float2 p3 = unpack2(acc[i][3]);
        float4 r0, r1;
        r0.x = p0.x + bias[n+0]; r0.y = p0.y + bias[n+1];
        r0.z = p1.x + bias[n+2]; r0.w = p1.y + bias[n+3];
        r1.x = p2.x + bias[n+4]; r1.y = p2.y + bias[n+5];
        r1.z = p3.x + bias[n+6]; r1.w = p3.y + bias[n+7];
        *(float4*)&Out[(size_t)m * N + n]     = r0;
        *(float4*)&Out[(size_t)m * N + n + 4] = r1;
    }
}

// ---------------------------------------------------------------------------
// Scores: s[b,i,j] = sum_d Ws[d]*tanh(q[b,i,d]+k[b,j,d]) + bs  (MUFU-bound)
// ---------------------------------------------------------------------------
__global__ __launch_bounds__(256) void score_kernel(const float* __restrict__ Ws,
                                                    const float* __restrict__ bsp)
{
    const int bz = blockIdx.z;
    const int q0 = blockIdx.y * 32;
    const int k0 = blockIdx.x * 32;

    __shared__ float Qs[32][65];
    __shared__ float Ks[32][65];
    __shared__ float Wss[64];

    const int t  = threadIdx.x;
    const int tx = t & 15, ty = t >> 4;

    float acc00 = 0.f, acc01 = 0.f, acc10 = 0.f, acc11 = 0.f;

    const float* qb = g_q + ((size_t)bz*LQ + q0) * DD;
    const float* kb = g_k + ((size_t)bz*LK + k0) * DD;

    const int lrow = t >> 3;
    const int lcol = (t & 7) * 8;

    for (int d0 = 0; d0 < DD; d0 += 64) {
        float4 x0 = *(const float4*)&qb[(size_t)lrow*DD + d0 + lcol];
        float4 x1 = *(const float4*)&qb[(size_t)lrow*DD + d0 + lcol + 4];
        Qs[lrow][lcol+0] = x0.x; Qs[lrow][lcol+1] = x0.y;
        Qs[lrow][lcol+2] = x0.z; Qs[lrow][lcol+3] = x0.w;
        Qs[lrow][lcol+4] = x1.x; Qs[lrow][lcol+5] = x1.y;
        Qs[lrow][lcol+6] = x1.z; Qs[lrow][lcol+7] = x1.w;
        float4 y0 = *(const float4*)&kb[(size_t)lrow*DD + d0 + lcol];
        float4 y1 = *(const float4*)&kb[(size_t)lrow*DD + d0 + lcol + 4];
        Ks[lrow][lcol+0] = y0.x; Ks[lrow][lcol+1] = y0.y;
        Ks[lrow][lcol+2] = y0.z; Ks[lrow][lcol+3] = y0.w;
        Ks[lrow][lcol+4] = y1.x; Ks[lrow][lcol+5] = y1.y;
        Ks[lrow][lcol+6] = y1.z; Ks[lrow][lcol+7] = y1.w;
        if (t < 16) *(float4*)&Wss[t*4] = *(const float4*)&Ws[d0 + t*4];
        __syncthreads();

        #pragma unroll 16
        for (int d = 0; d < 64; d++) {
            const float w  = Wss[d];
            const float qa = Qs[ty*2+0][d];
            const float qc = Qs[ty*2+1][d];
            const float ka = Ks[tx*2+0][d];
            const float kc = Ks[tx*2+1][d];
            acc00 = fmaf(w, tanh_fast(qa + ka), acc00);
            acc01 = fmaf(w, tanh_fast(qa + kc), acc01);
            acc10 = fmaf(w, tanh_fast(qc + ka), acc10);
            acc11 = fmaf(w, tanh_fast(qc + kc), acc11);
        }
        __syncthreads();
    }

    const float bsv = *bsp;
    float* sp = g_scores + ((size_t)bz*LQ + q0) * LK + k0;
    sp[(ty*2+0)*LK + tx*2+0] = acc00 + bsv;
    sp[(ty*2+0)*LK + tx*2+1] = acc01 + bsv;
    sp[(ty*2+1)*LK + tx*2+0] = acc10 + bsv;
    sp[(ty*2+1)*LK + tx*2+1] = acc11 + bsv;
}

// ---------------------------------------------------------------------------
// Row softmax over LK=256. One block (256 threads) per (b,q) row.
// ---------------------------------------------------------------------------
__global__ __launch_bounds__(256) void softmax_kernel(float* __restrict__ wout)
{
    const int row = blockIdx.x;
    const int t   = threadIdx.x;
    __shared__ float red[8];

    const float v = g_scores[(size_t)row*LK + t];

    float m = v;
    #pragma unroll
    for (int o = 16; o > 0; o >>= 1) m = fmaxf(m, __shfl_xor_sync(0xffffffffu, m, o));
    if ((t & 31) == 0) red[t >> 5] = m;
    __syncthreads();
    float mx = red[0];
    #pragma unroll
    for (int i = 1; i < 8; i++) mx = fmaxf(mx, red[i]);
    __syncthreads();

    const float e = __expf(v - mx);
    float s = e;
    #pragma unroll
    for (int o = 16; o > 0; o >>= 1) s += __shfl_xor_sync(0xffffffffu, s, o);
    if ((t & 31) == 0) red[t >> 5] = s;
    __syncthreads();
    float sum = 0.f;
    #pragma unroll
    for (int i = 0; i < 8; i++) sum += red[i];

    wout[(size_t)row*LK + t] = e * (1.0f / sum);
}

// ---------------------------------------------------------------------------
// attended = weights @ v : batched GEMM  M=LQ(q), N=DD(d), K=LK(j).
// 32q x 64d tile, 128 threads, BK=32 double-buffered, grid 384 (~2.6/SM).
// W tile stored transposed + DUPLICATED: Wt2[j][2q]={w,w}. Micro 4q x 4d.
// ---------------------------------------------------------------------------
__global__ __launch_bounds__(128) void av_kernel(const float* __restrict__ wts,
                                                 float* __restrict__ out)
{
    const int b  = blockIdx.z;
    const int q0 = blockIdx.y * 32;
    const int d0 = blockIdx.x * 64;

    __shared__ float Wt2[2][32][68];   // [j][2q] duplicated; row 272B (16B-mult)
    __shared__ float Vt [2][32][68];   // [j][d]; padded row

    const int t  = threadIdx.x;        // 0..127
    const int tx = t & 15;             // d = tx*4 (2 pairs)
    const int ty = t >> 4;             // 0..7, q = ty*4

    unsigned long long acc[4][2];
    #pragma unroll
    for (int i = 0; i < 4; i++) { acc[i][0] = 0ull; acc[i][1] = 0ull; }

    // W tile: 32q x 32j = 1024 floats, 8/thread (2 float4)
    const int wq = t >> 2;             // 0..31
    const int wj = (t & 3) * 8;        // 0,8,16,24
    // V tile: 32j x 64d = 2048 floats, 16/thread (4 float4)
    const int vr = t >> 2;             // 0..31
    const int vc = (t & 3) * 16;       // 0,16,32,48

    const float* wp = wts + ((size_t)b*LQ + q0 + wq) * LK + wj;
    const float* vp = g_v + ((size_t)b*LK + vr) * DD + d0 + vc;

    float4 pw0 = *(const float4*)(wp);
    float4 pw1 = *(const float4*)(wp + 4);
    float4 pv0 = *(const float4*)(vp);
    float4 pv1 = *(const float4*)(vp + 4);
    float4 pv2 = *(const float4*)(vp + 8);
    float4 pv3 = *(const float4*)(vp + 12);

    int buf = 0;
    for (int j0 = 0; j0 < LK; j0 += 32) {
        *(float2*)&Wt2[buf][wj+0][2*wq] = dup2(pw0.x);
        *(float2*)&Wt2[buf][wj+1][2*wq] = dup2(pw0.y);
        *(float2*)&Wt2[buf][wj+2][2*wq] = dup2(pw0.z);
        *(float2*)&Wt2[buf][wj+3][2*wq] = dup2(pw0.w);
        *(float2*)&Wt2[buf][wj+4][2*wq] = dup2(pw1.x);
        *(float2*)&Wt2[buf][wj+5][2*wq] = dup2(pw1.y);
        *(float2*)&Wt2[buf][wj+6][2*wq] = dup2(pw1.z);
        *(float2*)&Wt2[buf][wj+7][2*wq] = dup2(pw1.w);
        *(float4*)&Vt[buf][vr][vc +  0] = pv0;
        *(float4*)&Vt[buf][vr][vc +  4] = pv1;
        *(float4*)&Vt[buf][vr][vc +  8] = pv2;
        *(float4*)&Vt[buf][vr][vc + 12] = pv3;
        __syncthreads();

        if (j0 + 32 < LK) {
            pw0 = *(const float4*)(wp + j0 + 32);
            pw1 = *(const float4*)(wp + j0 + 36);
            const float* vpn = vp + (size_t)(j0 + 32) * DD;
            pv0 = *(const float4*)(vpn);
            pv1 = *(const float4*)(vpn + 4);
            pv2 = *(const float4*)(vpn + 8);
            pv3 = *(const float4*)(vpn + 12);
        }

        #pragma unroll 8
        for (int kk = 0; kk < 32; kk++) {
            ulonglong2 w01 = *(const ulonglong2*)&Wt2[buf][kk][ty*8];      // {w0,w0},{w1,w1}
            ulonglong2 w23 = *(const ulonglong2*)&Wt2[buf][kk][ty*8 + 4];  // {w2,w2},{w3,w3}
            ulonglong2 vv  = *(const ulonglong2*)&Vt[buf][kk][tx*4];       // {v0,v1},{v2,v3}
            ffma2(acc[0][0], w01.x, vv.x);
            ffma2(acc[0][1], w01.x, vv.y);
            ffma2(acc[1][0], w01.y, vv.x);
            ffma2(acc[1][1], w01.y, vv.y);
            ffma2(acc[2][0], w23.x, vv.x);
            ffma2(acc[2][1], w23.x, vv.y);
            ffma2(acc[3][0], w23.y, vv.x);
            ffma2(acc[3][1], w23.y, vv.y);
        }
        buf ^= 1;
    }

    #pragma unroll
    for (int i = 0; i < 4; i++) {
        float2 p0 = unpack2(acc[i][0]);
        float2 p1 = unpack2(acc[i][1]);
        float4 r = { p0.x, p0.y, p1.x, p1.y };
        *(float4*)&out[((size_t)b*LQ + q0 + ty*4 + i) * DD + d0 + tx*4] = r;
    }
}

// ---------------------------------------------------------------------------
extern "C" void kernel_launch(void* const* d_in, const int* in_sizes, int n_in,
                              void* d_out, int out_size)
{
    const float* query = (const float*)d_in[0];
    const float* key   = (const float*)d_in[1];
    const float* value = (const float*)d_in[2];
    const float* Wq    = (const float*)d_in[3];
    const float* bq    = (const float*)d_in[4];
    const float* Wk    = (const float*)d_in[5];
    const float* bk    = (const float*)d_in[6];
    const float* Wv    = (const float*)d_in[7];
    const float* bv    = (const float*)d_in[8];
    const float* Ws    = (const float*)d_in[9];
    const float* bs    = (const float*)d_in[10];

    float* att = (float*)d_out;                  // [B,LQ,D]
    float* wts = att + (size_t)BB * LQ * DD;     // [B,LQ,LK]

    proj_kernel<<<dim3(DD/128, (BB*LQ)/64, 3), 256>>>(
        query, key, value, Wq, bq, Wk, bk, Wv, bv);

    score_kernel<<<dim3(LK/32, LQ/32, BB), 256>>>(Ws, bs);

    softmax_kernel<<<BB*LQ, 256>>>(wts);

    av_kernel<<<dim3(DD/64, LQ/32, BB), 128>>>(wts, att);
}

// round 6
// speedup vs baseline: 1.6687x; 1.6687x over previous
#include <cuda_runtime.h>
#include <cstdint>

#define BB 4
#define LQ 256
#define LK 256
#define DD 768

// Scratch (no cudaMalloc allowed)
__device__ float g_q[BB*LQ*DD];
__device__ float g_k[BB*LK*DD];
__device__ float g_v[BB*LK*DD];
__device__ float g_scores[BB*LQ*LK];

__device__ __forceinline__ float tanh_fast(float x) {
    float y;
    asm("tanh.approx.f32 %0, %1;" : "=f"(y) : "f"(x));
    return y;
}

// ---- packed fp32x2 helpers (FFMA2 path, used in av) ----
__device__ __forceinline__ void ffma2(unsigned long long& acc,
                                      unsigned long long a,
                                      unsigned long long b) {
    asm("fma.rn.f32x2 %0, %1, %2, %0;" : "+l"(acc) : "l"(a), "l"(b));
}
__device__ __forceinline__ float2 unpack2(unsigned long long v) {
    float lo, hi;
    asm("mov.b64 {%0, %1}, %2;" : "=f"(lo), "=f"(hi) : "l"(v));
    return make_float2(lo, hi);
}
__device__ __forceinline__ float2 dup2(float x) { return make_float2(x, x); }

// ---- tf32 helpers ----
__device__ __forceinline__ uint32_t f2tf32(float x) {
    uint32_t u;
    asm("cvt.rna.tf32.f32 %0, %1;" : "=r"(u) : "f"(x));
    return u;
}
__device__ __forceinline__ void mma_tf32(float& d0, float& d1, float& d2, float& d3,
                                         uint32_t a0, uint32_t a1, uint32_t a2, uint32_t a3,
                                         uint32_t b0, uint32_t b1) {
    asm("mma.sync.aligned.m16n8k8.row.col.f32.tf32.tf32.f32 "
        "{%0,%1,%2,%3}, {%4,%5,%6,%7}, {%8,%9}, {%0,%1,%2,%3};"
        : "+f"(d0), "+f"(d1), "+f"(d2), "+f"(d3)
        : "r"(a0), "r"(a1), "r"(a2), "r"(a3), "r"(b0), "r"(b1));
}

// ---------------------------------------------------------------------------
// Projection GEMM via tf32 tensor cores.
// Out[M,N] = X[M,K] @ W[K,N] + b[N].  M=1024 (B*LQ), N=K=768.
// Block: 256 thr (8 warps, 2Mx4N warp grid), tile 64(M)x128(N), BK=32,
// double-buffered smem, cvt to tf32 on store. Warp tile 32x32 via m16n8k8.
// Grid (6, 16, 3) = 288 blocks (~2/SM).
// ---------------------------------------------------------------------------
__global__ __launch_bounds__(256) void proj_kernel(
    const float* __restrict__ xq, const float* __restrict__ xk, const float* __restrict__ xv,
    const float* __restrict__ Wq, const float* __restrict__ bq,
    const float* __restrict__ Wk, const float* __restrict__ bk,
    const float* __restrict__ Wv, const float* __restrict__ bv)
{
    const int N = DD, K = DD;
    const float *X, *W, *bias;
    float* Out;
    if (blockIdx.z == 0)      { X = xq; W = Wq; bias = bq; Out = g_q; }
    else if (blockIdx.z == 1) { X = xk; W = Wk; bias = bk; Out = g_k; }
    else                      { X = xv; W = Wv; bias = bv; Out = g_v; }

    __shared__ uint32_t As[2][64][36];    // [m][k] tf32, pad 36 (frag LDS conflict-free)
    __shared__ uint32_t Bsm[2][32][136];  // [k][n] tf32, pad 136 (frag LDS conflict-free)

    const int t    = threadIdx.x;         // 0..255
    const int wid  = t >> 5;              // 0..7
    const int lane = t & 31;
    const int wm   = wid & 1;             // warp m (x32)
    const int wn   = wid >> 1;            // warp n 0..3 (x32)
    const int grp  = lane >> 2;           // 0..7
    const int tig  = lane & 3;            // 0..3

    const int m0 = blockIdx.y * 64;
    const int n0 = blockIdx.x * 128;

    float acc[2][4][4];
    #pragma unroll
    for (int i = 0; i < 2; i++)
        #pragma unroll
        for (int j = 0; j < 4; j++)
            #pragma unroll
            for (int r = 0; r < 4; r++) acc[i][j][r] = 0.f;

    // A gmem load: 64 rows x 32 cols, 8 floats/thread
    const int ar = t >> 2, ac = (t & 3) * 8;
    // B gmem load: 32 rows x 128 cols, 16 floats/thread
    const int br = t >> 3, bc = (t & 7) * 16;

    const float* Xp = X + (size_t)(m0 + ar) * K + ac;
    const float* Wp = W + (size_t)br * N + n0 + bc;

    float4 pa0 = *(const float4*)(Xp);
    float4 pa1 = *(const float4*)(Xp + 4);
    float4 pb[4];
    #pragma unroll
    for (int u = 0; u < 4; u++) pb[u] = *(const float4*)(Wp + u*4);

    int buf = 0;
    for (int k0 = 0; k0 < K; k0 += 32) {
        // store tile (cvt to tf32)
        {
            uint4 ua0 = { f2tf32(pa0.x), f2tf32(pa0.y), f2tf32(pa0.z), f2tf32(pa0.w) };
            uint4 ua1 = { f2tf32(pa1.x), f2tf32(pa1.y), f2tf32(pa1.z), f2tf32(pa1.w) };
            *(uint4*)&As[buf][ar][ac]     = ua0;
            *(uint4*)&As[buf][ar][ac + 4] = ua1;
            #pragma unroll
            for (int u = 0; u < 4; u++) {
                uint4 ub = { f2tf32(pb[u].x), f2tf32(pb[u].y), f2tf32(pb[u].z), f2tf32(pb[u].w) };
                *(uint4*)&Bsm[buf][br][bc + u*4] = ub;
            }
        }
        __syncthreads();

        if (k0 + 32 < K) {
            pa0 = *(const float4*)(Xp + k0 + 32);
            pa1 = *(const float4*)(Xp + k0 + 36);
            const float* wpn = Wp + (size_t)(k0 + 32) * N;
            #pragma unroll
            for (int u = 0; u < 4; u++) pb[u] = *(const float4*)(wpn + u*4);
        }

        #pragma unroll
        for (int ks = 0; ks < 4; ks++) {
            const int kb = ks * 8;
            // A fragments (2 x m16k8)
            uint32_t a[2][4];
            #pragma unroll
            for (int mi = 0; mi < 2; mi++) {
                const int mb = wm*32 + mi*16;
                a[mi][0] = As[buf][mb + grp    ][kb + tig];
                a[mi][1] = As[buf][mb + grp + 8][kb + tig];
                a[mi][2] = As[buf][mb + grp    ][kb + tig + 4];
                a[mi][3] = As[buf][mb + grp + 8][kb + tig + 4];
            }
            // B fragments (4 x k8n8)
            uint32_t b[4][2];
            #pragma unroll
            for (int ni = 0; ni < 4; ni++) {
                const int nb = wn*32 + ni*8;
                b[ni][0] = Bsm[buf][kb + tig    ][nb + grp];
                b[ni][1] = Bsm[buf][kb + tig + 4][nb + grp];
            }
            #pragma unroll
            for (int mi = 0; mi < 2; mi++)
                #pragma unroll
                for (int ni = 0; ni < 4; ni++)
                    mma_tf32(acc[mi][ni][0], acc[mi][ni][1], acc[mi][ni][2], acc[mi][ni][3],
                             a[mi][0], a[mi][1], a[mi][2], a[mi][3],
                             b[ni][0], b[ni][1]);
        }
        __syncthreads();
        buf ^= 1;
    }

    // epilogue: D[row][col], row = m0+wm*32+mi*16+grp(+8), col = n0+wn*32+ni*8+2*tig(+1)
    #pragma unroll
    for (int mi = 0; mi < 2; mi++) {
        #pragma unroll
        for (int ni = 0; ni < 4; ni++) {
            const int col = n0 + wn*32 + ni*8 + 2*tig;
            const float b0 = bias[col], b1 = bias[col+1];
            const int r0 = m0 + wm*32 + mi*16 + grp;
            const int r1 = r0 + 8;
            float2 lo = { acc[mi][ni][0] + b0, acc[mi][ni][1] + b1 };
            float2 hi = { acc[mi][ni][2] + b0, acc[mi][ni][3] + b1 };
            *(float2*)&Out[(size_t)r0 * N + col] = lo;
            *(float2*)&Out[(size_t)r1 * N + col] = hi;
        }
    }
}

// ---------------------------------------------------------------------------
// Scores: s[b,i,j] = sum_d Ws[d]*tanh(q[b,i,d]+k[b,j,d]) + bs  (MUFU-bound)
// ---------------------------------------------------------------------------
__global__ __launch_bounds__(256) void score_kernel(const float* __restrict__ Ws,
                                                    const float* __restrict__ bsp)
{
    const int bz = blockIdx.z;
    const int q0 = blockIdx.y * 32;
    const int k0 = blockIdx.x * 32;

    __shared__ float Qs[32][65];
    __shared__ float Ks[32][65];
    __shared__ float Wss[64];

    const int t  = threadIdx.x;
    const int tx = t & 15, ty = t >> 4;

    float acc00 = 0.f, acc01 = 0.f, acc10 = 0.f, acc11 = 0.f;

    const float* qb = g_q + ((size_t)bz*LQ + q0) * DD;
    const float* kb = g_k + ((size_t)bz*LK + k0) * DD;

    const int lrow = t >> 3;
    const int lcol = (t & 7) * 8;

    for (int d0 = 0; d0 < DD; d0 += 64) {
        float4 x0 = *(const float4*)&qb[(size_t)lrow*DD + d0 + lcol];
        float4 x1 = *(const float4*)&qb[(size_t)lrow*DD + d0 + lcol + 4];
        Qs[lrow][lcol+0] = x0.x; Qs[lrow][lcol+1] = x0.y;
        Qs[lrow][lcol+2] = x0.z; Qs[lrow][lcol+3] = x0.w;
        Qs[lrow][lcol+4] = x1.x; Qs[lrow][lcol+5] = x1.y;
        Qs[lrow][lcol+6] = x1.z; Qs[lrow][lcol+7] = x1.w;
        float4 y0 = *(const float4*)&kb[(size_t)lrow*DD + d0 + lcol];
        float4 y1 = *(const float4*)&kb[(size_t)lrow*DD + d0 + lcol + 4];
        Ks[lrow][lcol+0] = y0.x; Ks[lrow][lcol+1] = y0.y;
        Ks[lrow][lcol+2] = y0.z; Ks[lrow][lcol+3] = y0.w;
        Ks[lrow][lcol+4] = y1.x; Ks[lrow][lcol+5] = y1.y;
        Ks[lrow][lcol+6] = y1.z; Ks[lrow][lcol+7] = y1.w;
        if (t < 16) *(float4*)&Wss[t*4] = *(const float4*)&Ws[d0 + t*4];
        __syncthreads();

        #pragma unroll 16
        for (int d = 0; d < 64; d++) {
            const float w  = Wss[d];
            const float qa = Qs[ty*2+0][d];
            const float qc = Qs[ty*2+1][d];
            const float ka = Ks[tx*2+0][d];
            const float kc = Ks[tx*2+1][d];
            acc00 = fmaf(w, tanh_fast(qa + ka), acc00);
            acc01 = fmaf(w, tanh_fast(qa + kc), acc01);
            acc10 = fmaf(w, tanh_fast(qc + ka), acc10);
            acc11 = fmaf(w, tanh_fast(qc + kc), acc11);
        }
        __syncthreads();
    }

    const float bsv = *bsp;
    float* sp = g_scores + ((size_t)bz*LQ + q0) * LK + k0;
    sp[(ty*2+0)*LK + tx*2+0] = acc00 + bsv;
    sp[(ty*2+0)*LK + tx*2+1] = acc01 + bsv;
    sp[(ty*2+1)*LK + tx*2+0] = acc10 + bsv;
    sp[(ty*2+1)*LK + tx*2+1] = acc11 + bsv;
}

// ---------------------------------------------------------------------------
// Row softmax over LK=256. One block (256 threads) per (b,q) row.
// ---------------------------------------------------------------------------
__global__ __launch_bounds__(256) void softmax_kernel(float* __restrict__ wout)
{
    const int row = blockIdx.x;
    const int t   = threadIdx.x;
    __shared__ float red[8];

    const float v = g_scores[(size_t)row*LK + t];

    float m = v;
    #pragma unroll
    for (int o = 16; o > 0; o >>= 1) m = fmaxf(m, __shfl_xor_sync(0xffffffffu, m, o));
    if ((t & 31) == 0) red[t >> 5] = m;
    __syncthreads();
    float mx = red[0];
    #pragma unroll
    for (int i = 1; i < 8; i++) mx = fmaxf(mx, red[i]);
    __syncthreads();

    const float e = __expf(v - mx);
    float s = e;
    #pragma unroll
    for (int o = 16; o > 0; o >>= 1) s += __shfl_xor_sync(0xffffffffu, s, o);
    if ((t & 31) == 0) red[t >> 5] = s;
    __syncthreads();
    float sum = 0.f;
    #pragma unroll
    for (int i = 0; i < 8; i++) sum += red[i];

    wout[(size_t)row*LK + t] = e * (1.0f / sum);
}

// ---------------------------------------------------------------------------
// attended = weights @ v : batched GEMM  M=LQ(q), N=DD(d), K=LK(j).
// 32q x 64d tile, 128 threads, BK=32 double-buffered, grid 384 (~2.6/SM).
// W tile stored transposed + DUPLICATED: Wt2[j][2q]={w,w}. Micro 4q x 4d.
// ---------------------------------------------------------------------------
__global__ __launch_bounds__(128) void av_kernel(const float* __restrict__ wts,
                                                 float* __restrict__ out)
{
    const int b  = blockIdx.z;
    const int q0 = blockIdx.y * 32;
    const int d0 = blockIdx.x * 64;

    __shared__ float Wt2[2][32][68];   // [j][2q] duplicated
    __shared__ float Vt [2][32][68];   // [j][d]

    const int t  = threadIdx.x;        // 0..127
    const int tx = t & 15;             // d = tx*4 (2 pairs)
    const int ty = t >> 4;             // 0..7, q = ty*4

    unsigned long long acc[4][2];
    #pragma unroll
    for (int i = 0; i < 4; i++) { acc[i][0] = 0ull; acc[i][1] = 0ull; }

    const int wq = t >> 2;             // 0..31
    const int wj = (t & 3) * 8;        // 0,8,16,24
    const int vr = t >> 2;             // 0..31
    const int vc = (t & 3) * 16;       // 0,16,32,48

    const float* wp = wts + ((size_t)b*LQ + q0 + wq) * LK + wj;
    const float* vp = g_v + ((size_t)b*LK + vr) * DD + d0 + vc;

    float4 pw0 = *(const float4*)(wp);
    float4 pw1 = *(const float4*)(wp + 4);
    float4 pv0 = *(const float4*)(vp);
    float4 pv1 = *(const float4*)(vp + 4);
    float4 pv2 = *(const float4*)(vp + 8);
    float4 pv3 = *(const float4*)(vp + 12);

    int buf = 0;
    for (int j0 = 0; j0 < LK; j0 += 32) {
        *(float2*)&Wt2[buf][wj+0][2*wq] = dup2(pw0.x);
        *(float2*)&Wt2[buf][wj+1][2*wq] = dup2(pw0.y);
        *(float2*)&Wt2[buf][wj+2][2*wq] = dup2(pw0.z);
        *(float2*)&Wt2[buf][wj+3][2*wq] = dup2(pw0.w);
        *(float2*)&Wt2[buf][wj+4][2*wq] = dup2(pw1.x);
        *(float2*)&Wt2[buf][wj+5][2*wq] = dup2(pw1.y);
        *(float2*)&Wt2[buf][wj+6][2*wq] = dup2(pw1.z);
        *(float2*)&Wt2[buf][wj+7][2*wq] = dup2(pw1.w);
        *(float4*)&Vt[buf][vr][vc +  0] = pv0;
        *(float4*)&Vt[buf][vr][vc +  4] = pv1;
        *(float4*)&Vt[buf][vr][vc +  8] = pv2;
        *(float4*)&Vt[buf][vr][vc + 12] = pv3;
        __syncthreads();

        if (j0 + 32 < LK) {
            pw0 = *(const float4*)(wp + j0 + 32);
            pw1 = *(const float4*)(wp + j0 + 36);
            const float* vpn = vp + (size_t)(j0 + 32) * DD;
            pv0 = *(const float4*)(vpn);
            pv1 = *(const float4*)(vpn + 4);
            pv2 = *(const float4*)(vpn + 8);
            pv3 = *(const float4*)(vpn + 12);
        }

        #pragma unroll 8
        for (int kk = 0; kk < 32; kk++) {
            ulonglong2 w01 = *(const ulonglong2*)&Wt2[buf][kk][ty*8];
            ulonglong2 w23 = *(const ulonglong2*)&Wt2[buf][kk][ty*8 + 4];
            ulonglong2 vv  = *(const ulonglong2*)&Vt[buf][kk][tx*4];
            ffma2(acc[0][0], w01.x, vv.x);
            ffma2(acc[0][1], w01.x, vv.y);
            ffma2(acc[1][0], w01.y, vv.x);
            ffma2(acc[1][1], w01.y, vv.y);
            ffma2(acc[2][0], w23.x, vv.x);
            ffma2(acc[2][1], w23.x, vv.y);
            ffma2(acc[3][0], w23.y, vv.x);
            ffma2(acc[3][1], w23.y, vv.y);
        }
        buf ^= 1;
    }

    #pragma unroll
    for (int i = 0; i < 4; i++) {
        float2 p0 = unpack2(acc[i][0]);
        float2 p1 = unpack2(acc[i][1]);
        float4 r = { p0.x, p0.y, p1.x, p1.y };
        *(float4*)&out[((size_t)b*LQ + q0 + ty*4 + i) * DD + d0 + tx*4] = r;
    }
}

// ---------------------------------------------------------------------------
extern "C" void kernel_launch(void* const* d_in, const int* in_sizes, int n_in,
                              void* d_out, int out_size)
{
    const float* query = (const float*)d_in[0];
    const float* key   = (const float*)d_in[1];
    const float* value = (const float*)d_in[2];
    const float* Wq    = (const float*)d_in[3];
    const float* bq    = (const float*)d_in[4];
    const float* Wk    = (const float*)d_in[5];
    const float* bk    = (const float*)d_in[6];
    const float* Wv    = (const float*)d_in[7];
    const float* bv    = (const float*)d_in[8];
    const float* Ws    = (const float*)d_in[9];
    const float* bs    = (const float*)d_in[10];

    float* att = (float*)d_out;                  // [B,LQ,D]
    float* wts = att + (size_t)BB * LQ * DD;     // [B,LQ,LK]

    proj_kernel<<<dim3(DD/128, (BB*LQ)/64, 3), 256>>>(
        query, key, value, Wq, bq, Wk, bk, Wv, bv);

    score_kernel<<<dim3(LK/32, LQ/32, BB), 256>>>(Ws, bs);

    softmax_kernel<<<BB*LQ, 256>>>(wts);

    av_kernel<<<dim3(DD/64, LQ/32, BB), 128>>>(wts, att);
}